// round 7
// baseline (speedup 1.0000x reference)
#include <cuda_runtime.h>
#include <cuda_bf16.h>
#include <cstdint>

// ---------------------------------------------------------------------------
// SuperpixelAttention GB300 — Round 6: head-split halo attention (2 blocks/SM)
//   conv_x : x fp32 -> g_x2 [pix][hi256|lo256] bf16
//   conv_w : Wq|Wk|Wv -> g_w1 (q scale folded), Wp -> g_w2
//   gemm(0): q/k/v fp32 (mma.sync bf16 3-term split)
//   attn   : 16x4 tiles, k/v halo in smem split into 2 head-groups (128 ch),
//            112.5KB smem/block -> 2 blocks/SM; writes g_o2 bf16 hi|lo
//   gemm(1): out = o @ Wp, transposed store to [T,C,H,W]
// ---------------------------------------------------------------------------

#define NPIX 262144
#define NELEM 67108864

__device__ float g_q[NELEM];
__device__ float g_k[NELEM];
__device__ float g_v[NELEM];
__device__ __nv_bfloat16 g_x2[NPIX * 512];
__device__ __nv_bfloat16 g_o2[NPIX * 512];
__device__ __nv_bfloat16 g_w1[768 * 512];
__device__ __nv_bfloat16 g_w2[256 * 512];

__device__ __forceinline__ uint32_t smem_u32(const void* p) {
  uint32_t a;
  asm("{ .reg .u64 t; cvta.to.shared.u64 t, %1; cvt.u32.u64 %0, t; }"
      : "=r"(a) : "l"(p));
  return a;
}
#define SW128(o) ((o) ^ (((o) >> 3) & 0x70))

__device__ __forceinline__ void ldsm4(uint32_t& r0, uint32_t& r1, uint32_t& r2,
                                      uint32_t& r3, uint32_t a) {
  asm volatile("ldmatrix.sync.aligned.m8n8.x4.shared.b16 {%0,%1,%2,%3}, [%4];"
               : "=r"(r0), "=r"(r1), "=r"(r2), "=r"(r3) : "r"(a));
}
__device__ __forceinline__ void mma16816(float* c, const uint32_t* a,
                                         const uint32_t* b) {
  asm volatile(
      "mma.sync.aligned.m16n8k16.row.col.f32.bf16.bf16.f32 "
      "{%0,%1,%2,%3},{%4,%5,%6,%7},{%8,%9},{%0,%1,%2,%3};"
      : "+f"(c[0]), "+f"(c[1]), "+f"(c[2]), "+f"(c[3])
      : "r"(a[0]), "r"(a[1]), "r"(a[2]), "r"(a[3]), "r"(b[0]), "r"(b[1]));
}
__device__ __forceinline__ void cp16(uint32_t s, const void* g) {
  asm volatile("cp.async.cg.shared.global [%0], [%1], 16;" :: "r"(s), "l"(g));
}

// ---------------------------------------------------------------------------
// Conversions
// ---------------------------------------------------------------------------
__global__ void __launch_bounds__(256) conv_x(const float* __restrict__ x) {
  extern __shared__ float xs[];  // 256 * 65
  const int tid = threadIdx.x;
  const int pix0 = blockIdx.x * 64;
  const int t = pix0 >> 16, h = (pix0 >> 8) & 255, w0 = pix0 & 255;
  const size_t base = (size_t)t * 16777216 + h * 256 + w0;
  for (int i = tid; i < 16384; i += 256) {
    int c = i >> 6, p = i & 63;
    xs[c * 65 + p] = x[base + (size_t)c * 65536 + p];
  }
  __syncthreads();
  for (int i = tid; i < 32768; i += 256) {
    int p = i >> 9, kk = i & 511, c = kk & 255;
    float v = xs[c * 65 + p];
    __nv_bfloat16 hi = __float2bfloat16_rn(v);
    __nv_bfloat16 o = (kk < 256) ? hi : __float2bfloat16_rn(v - __bfloat162float(hi));
    g_x2[(size_t)(pix0 + p) * 512 + kk] = o;
  }
}

__global__ void __launch_bounds__(256) conv_w(const float* __restrict__ Wq,
                                              const float* __restrict__ Wk,
                                              const float* __restrict__ Wv,
                                              const float* __restrict__ Wp) {
  const int n = blockIdx.x;   // 0..1023
  const int c = threadIdx.x;
  float v;
  __nv_bfloat16* dst;
  if (n < 768) {
    const float* Wm = (n < 256) ? Wq : ((n < 512) ? Wk : Wv);
    v = Wm[c * 256 + (n & 255)];
    if (n < 256) v *= 0.125f;  // fold hd^-0.5 into Wq
    dst = g_w1 + (size_t)n * 512;
  } else {
    v = Wp[c * 256 + (n & 255)];
    dst = g_w2 + (size_t)(n - 768) * 512;
  }
  __nv_bfloat16 hi = __float2bfloat16_rn(v);
  dst[c] = hi;
  dst[256 + c] = __float2bfloat16_rn(v - __bfloat162float(hi));
}

// ---------------------------------------------------------------------------
// mma.sync GEMM (unchanged from R4)
// ---------------------------------------------------------------------------
__global__ void __launch_bounds__(256) gemm_kernel(
    const __nv_bfloat16* __restrict__ A2,
    const __nv_bfloat16* __restrict__ B2,
    float* __restrict__ y, int mode) {
  extern __shared__ char dsm[];
  char* base = (char*)((((uintptr_t)dsm) + 1023) & ~(uintptr_t)1023);
  const uint32_t As_a = smem_u32(base);
  const uint32_t Bs_a0 = As_a + 131072u;
  float* ys = (float*)(base + 163840);

  const int tid = threadIdx.x, lane = tid & 31, wid = tid >> 5;
  const int wm = wid & 1, wn = wid >> 1;
  const int pix0 = blockIdx.x * 128;

  const uint4* Aq = (const uint4*)A2;
  for (int idx = tid; idx < 8192; idx += 256) {
    int ch = idx >> 10, row = (idx >> 3) & 127, c = idx & 7;
    *(uint4*)(base + ch * 16384 + SW128((uint32_t)(row * 128 + c * 16))) =
        Aq[(size_t)(pix0 + row) * 64 + ch * 8 + c];
  }

  const uint4* Bq = (const uint4*)B2;
  const int total = (mode ? 2 : 6) * 12;

  auto prefetchB = [&](int q) {
    int kc2 = q % 12, term = kc2 >> 2;
    int n0g = (q / 12) << 7;
    int b8 = ((term == 1) ? 32 : 0) + (kc2 & 3) * 8;
    uint32_t buf = Bs_a0 + (uint32_t)((q & 1) << 14);
    for (int idx = tid; idx < 1024; idx += 256) {
      int row = idx >> 3, c = idx & 7;
      cp16(buf + SW128((uint32_t)(row * 128 + c * 16)),
           &Bq[(size_t)(n0g + row) * 64 + b8 + c]);
    }
    asm volatile("cp.async.commit_group;" ::: "memory");
  };

  float acc[4][4][4];
#pragma unroll
  for (int i = 0; i < 4; i++)
#pragma unroll
    for (int j = 0; j < 4; j++)
#pragma unroll
      for (int r = 0; r < 4; r++) acc[i][j][r] = 0.f;

  prefetchB(0);

  const int arow_off = (lane & 7) + ((lane >> 3) & 1) * 8;
  const int ak_ex = ((lane >> 4) & 1) * 16;
  const int brow_off = (lane & 7) + ((lane >> 4) & 1) * 8;
  const int bk_ex = ((lane >> 3) & 1) * 16;

  for (int q = 0; q < total; ++q) {
    if (q + 1 < total) {
      prefetchB(q + 1);
      asm volatile("cp.async.wait_group 1;" ::: "memory");
    } else {
      asm volatile("cp.async.wait_group 0;" ::: "memory");
    }
    __syncthreads();

    const int kc2 = q % 12, term = kc2 >> 2;
    const uint32_t Ab = As_a + (uint32_t)((((term == 2) ? 4 : 0) + (kc2 & 3)) * 16384);
    const uint32_t Bb = Bs_a0 + (uint32_t)((q & 1) << 14);

#pragma unroll
    for (int s = 0; s < 4; ++s) {
      uint32_t af[4][4];
#pragma unroll
      for (int i = 0; i < 4; ++i) {
        uint32_t off = (uint32_t)((wm * 64 + i * 16 + arow_off) * 128 + s * 32 + ak_ex);
        ldsm4(af[i][0], af[i][1], af[i][2], af[i][3], Ab + SW128(off));
      }
      uint32_t bf[4][2];
#pragma unroll
      for (int j2 = 0; j2 < 2; ++j2) {
        uint32_t off = (uint32_t)((wn * 32 + j2 * 16 + brow_off) * 128 + s * 32 + bk_ex);
        ldsm4(bf[2 * j2][0], bf[2 * j2][1], bf[2 * j2 + 1][0], bf[2 * j2 + 1][1],
              Bb + SW128(off));
      }
#pragma unroll
      for (int i = 0; i < 4; ++i)
#pragma unroll
        for (int j = 0; j < 4; ++j) mma16816(acc[i][j], af[i], bf[j]);
    }

    if (kc2 == 11) {
      const int nc = q / 12;
      if (mode == 0) {
        float* dst = (nc < 2) ? g_q : (nc < 4) ? g_k : g_v;
        const int colb = (nc & 1) * 128 + wn * 32;
#pragma unroll
        for (int i = 0; i < 4; ++i) {
          int row0 = pix0 + wm * 64 + i * 16 + (lane >> 2);
#pragma unroll
          for (int j = 0; j < 4; ++j) {
            int col = colb + j * 8 + 2 * (lane & 3);
            *(float2*)(dst + (size_t)row0 * 256 + col) =
                make_float2(acc[i][j][0], acc[i][j][1]);
            *(float2*)(dst + (size_t)(row0 + 8) * 256 + col) =
                make_float2(acc[i][j][2], acc[i][j][3]);
          }
        }
      } else {
        const int t = pix0 >> 16, h = (pix0 >> 8) & 255, w0 = pix0 & 255;
        float* yb = y + (size_t)t * 16777216 + h * 256 + w0;
        for (int g = 0; g < 4; ++g) {
          if (wn == g) {
#pragma unroll
            for (int i = 0; i < 4; ++i) {
              int row0 = wm * 64 + i * 16 + (lane >> 2);
#pragma unroll
              for (int j = 0; j < 4; ++j) {
                int cl = j * 8 + 2 * (lane & 3);
                ys[cl * 132 + row0] = acc[i][j][0];
                ys[(cl + 1) * 132 + row0] = acc[i][j][1];
                ys[cl * 132 + row0 + 8] = acc[i][j][2];
                ys[(cl + 1) * 132 + row0 + 8] = acc[i][j][3];
              }
            }
          }
          __syncthreads();
          const int chb = nc * 128 + g * 32;
          for (int idx = tid; idx < 4096; idx += 256) {
            int cl = idx >> 7, p = idx & 127;
            yb[(size_t)(chb + cl) * 65536 + p] = ys[cl * 132 + p];
          }
          __syncthreads();
        }
      }
#pragma unroll
      for (int i = 0; i < 4; i++)
#pragma unroll
        for (int j = 0; j < 4; j++)
#pragma unroll
          for (int r = 0; r < 4; r++) acc[i][j][r] = 0.f;
    }
    __syncthreads();
  }
}

// ---------------------------------------------------------------------------
// Head-split tiled attention. Block = 16(w) x 4(h) px, 512 threads, 16 warps.
// Halo = 20x8 cells x 128 ch (one 2-head group) = 80KB, reloaded 4x
// (k:hg0, k:hg1, v:hg0, v:hg1). Warp = (r=wid&3, seg=wid>>2).
// Lane: hgrp=lane>>3 -> hh=hgrp&1 (head in group), jpar=hgrp>>1 (j parity),
// lane8=lane&7 -> 8 channels. smem: halo 80K | ls 26K (sims halo overlaid)
// | sd 6.5K = 112.5KB -> 2 blocks/SM.
// ---------------------------------------------------------------------------
__device__ __forceinline__ uint32_t packbf2(float a, float b) {
  __nv_bfloat162 h = __floats2bfloat162_rn(a, b);
  return *reinterpret_cast<uint32_t*>(&h);
}

__global__ void __launch_bounds__(512, 2) attn_kernel(const float* __restrict__ sims) {
  extern __shared__ float sm[];
  float* hs = sm;              // 20480 fl: halo 160 cells x 128 ch
  float* ls = sm + 20480;      // 6656 fl: logits/wts [64][4][26]
  float* sd = sm + 27136;      // 1664 fl: simdot [64][26]
  float* ss = ls;              // sims halo [9][160] overlaid on ls (dead after sd)

  const int tid = threadIdx.x, lane = tid & 31, wid = tid >> 5;
  const int bw = blockIdx.x & 15;
  const int bh = (blockIdx.x >> 4) & 63;
  const int t = blockIdx.x >> 10;
  const int w0 = bw << 4, h0 = bh << 2;

  const int r = wid & 3, seg = wid >> 2;
  const int hgrp = lane >> 3, hh = hgrp & 1, jpar = hgrp >> 1;
  const int lane8 = lane & 7;
  const size_t pixg0 = (size_t)((t << 16) | ((h0 + r) << 8) | (w0 + (seg << 2)));

  uint4* hs4 = (uint4*)hs;
  const float4* qg = (const float4*)g_q;

  auto load_halo = [&](const float* src, int hg) {
    const uint4* s4 = (const uint4*)src;
#pragma unroll 1
    for (int i = tid; i < 5120; i += 512) {
      int cell = i >> 5, c4 = i & 31;
      int rr = cell / 20, cc = cell - rr * 20;
      int gh = min(max(h0 - 2 + rr, 0), 255);
      int gw = min(max(w0 - 2 + cc, 0), 255);
      hs4[cell * 32 + c4] =
          s4[((size_t)((t << 16) | (gh << 8) | gw)) * 64 + hg * 32 + c4];
    }
  };

  // logits for one head group (heads 2*hg, 2*hg+1) from current k halo
  auto do_logits = [&](int hg) {
    float4 qa[4], qb[4];
#pragma unroll
    for (int p = 0; p < 4; ++p) {
      qa[p] = qg[(pixg0 + p) * 64 + hg * 32 + hh * 16 + lane8 * 2];
      qb[p] = qg[(pixg0 + p) * 64 + hg * 32 + hh * 16 + lane8 * 2 + 1];
    }
#pragma unroll 1
    for (int di = 0; di < 5; ++di) {
#pragma unroll
      for (int jp = 0; jp < 4; ++jp) {
        const int jj = jp * 2 + jpar;
        const float4* kr =
            (const float4*)(hs + (((r + di) * 20 + (seg << 2) + jj) << 7) +
                            hh * 64 + lane8 * 8);
        float4 ka = kr[0], kb = kr[1];
        const int plo = (jj - 4 > 0) ? jj - 4 : 0;
        const int phi = (jj < 3) ? jj : 3;
#pragma unroll
        for (int p = plo; p <= phi; ++p) {
          float d = qa[p].x * ka.x + qa[p].y * ka.y + qa[p].z * ka.z +
                    qa[p].w * ka.w + qb[p].x * kb.x + qb[p].y * kb.y +
                    qb[p].z * kb.z + qb[p].w * kb.w;
          d += __shfl_xor_sync(0xffffffffu, d, 1);
          d += __shfl_xor_sync(0xffffffffu, d, 2);
          d += __shfl_xor_sync(0xffffffffu, d, 4);
          if (lane8 == 0) {
            int px = (r << 4) + (seg << 2) + p;
            ls[(px * 4 + hg * 2 + hh) * 26 + di * 5 + jj - p] = d;
          }
        }
      }
    }
  };

  // weighted v accumulate + store for one head group
  auto do_accum = [&](int hg) {
    float acc[4][8];
#pragma unroll
    for (int p = 0; p < 4; ++p)
#pragma unroll
      for (int c = 0; c < 8; ++c) acc[p][c] = 0.f;
#pragma unroll 1
    for (int di = 0; di < 5; ++di) {
#pragma unroll
      for (int jp = 0; jp < 4; ++jp) {
        const int jj = jp * 2 + jpar;
        const float4* vr =
            (const float4*)(hs + (((r + di) * 20 + (seg << 2) + jj) << 7) +
                            hh * 64 + lane8 * 8);
        float4 va = vr[0], vb = vr[1];
        const int plo = (jj - 4 > 0) ? jj - 4 : 0;
        const int phi = (jj < 3) ? jj : 3;
#pragma unroll
        for (int p = plo; p <= phi; ++p) {
          int px = (r << 4) + (seg << 2) + p;
          float wt = ls[(px * 4 + hg * 2 + hh) * 26 + di * 5 + jj - p];
          acc[p][0] += wt * va.x; acc[p][1] += wt * va.y;
          acc[p][2] += wt * va.z; acc[p][3] += wt * va.w;
          acc[p][4] += wt * vb.x; acc[p][5] += wt * vb.y;
          acc[p][6] += wt * vb.z; acc[p][7] += wt * vb.w;
        }
      }
    }
    // merge j-parity halves (hgrp ^ 2)
#pragma unroll
    for (int p = 0; p < 4; ++p)
#pragma unroll
      for (int c = 0; c < 8; ++c)
        acc[p][c] += __shfl_xor_sync(0xffffffffu, acc[p][c], 16);
    if (jpar == 0) {
      uint4* oq = (uint4*)g_o2;
#pragma unroll
      for (int p = 0; p < 4; ++p) {
        float hi[8], lo[8];
#pragma unroll
        for (int c = 0; c < 8; ++c) {
          hi[c] = __bfloat162float(__float2bfloat16_rn(acc[p][c]));
          lo[c] = acc[p][c] - hi[c];
        }
        uint4 hv, lv;
        hv.x = packbf2(hi[0], hi[1]); hv.y = packbf2(hi[2], hi[3]);
        hv.z = packbf2(hi[4], hi[5]); hv.w = packbf2(hi[6], hi[7]);
        lv.x = packbf2(lo[0], lo[1]); lv.y = packbf2(lo[2], lo[3]);
        lv.z = packbf2(lo[4], lo[5]); lv.w = packbf2(lo[6], lo[7]);
        size_t ob = (pixg0 + p) * 64 + hg * 16 + hh * 8 + lane8;
        oq[ob] = hv;
        oq[ob + 32] = lv;
      }
    }
  };

  // ---- P0: k halo (hg0) + sims halo; simdot ----
  load_halo(g_k, 0);
  for (int i = tid; i < 1440; i += 512) {
    int s = i / 160, cell = i - s * 160;
    int rr = cell / 20, cc = cell - rr * 20;
    int gh = min(max(h0 - 2 + rr, 0), 255);
    int gw = min(max(w0 - 2 + cc, 0), 255);
    ss[i] = sims[(size_t)(((t * 9 + s) << 16) | (gh << 8) | gw)];
  }
  __syncthreads();
  for (int i = tid; i < 1600; i += 512) {
    int px = i / 25, tap = i - px * 25;
    int rr = px >> 4, wc = px & 15;
    int di = tap / 5, dj = tap - di * 5;
    int ctr = (rr + 2) * 20 + wc + 2;
    int nbc = (rr + di) * 20 + wc + dj;
    float a = 0.f;
#pragma unroll
    for (int s = 0; s < 9; ++s) a += ss[s * 160 + ctr] * ss[s * 160 + nbc];
    sd[px * 26 + tap] = a;
  }
  __syncthreads();

  // ---- P1a: logits heads 0,1 ----
  do_logits(0);
  __syncthreads();
  // ---- P1b: k halo (hg1), logits heads 2,3 ----
  load_halo(g_k, 1);
  __syncthreads();
  do_logits(1);
  __syncthreads();

  // ---- softmax + sim reweight (in place in ls) ----
#pragma unroll 1
  for (int p = 0; p < 4; ++p) {
    const int px = (r << 4) + (seg << 2) + p;
#pragma unroll 1
    for (int h4 = 0; h4 < 4; ++h4) {
      float a = (lane < 25) ? ls[(px * 4 + h4) * 26 + lane] : -1e30f;
      float mx = a;
      mx = fmaxf(mx, __shfl_xor_sync(0xffffffffu, mx, 16));
      mx = fmaxf(mx, __shfl_xor_sync(0xffffffffu, mx, 8));
      mx = fmaxf(mx, __shfl_xor_sync(0xffffffffu, mx, 4));
      mx = fmaxf(mx, __shfl_xor_sync(0xffffffffu, mx, 2));
      mx = fmaxf(mx, __shfl_xor_sync(0xffffffffu, mx, 1));
      float e = (lane < 25) ? expf(a - mx) * sd[px * 26 + lane] : 0.f;
      float s = e;
      s += __shfl_xor_sync(0xffffffffu, s, 16);
      s += __shfl_xor_sync(0xffffffffu, s, 8);
      s += __shfl_xor_sync(0xffffffffu, s, 4);
      s += __shfl_xor_sync(0xffffffffu, s, 2);
      s += __shfl_xor_sync(0xffffffffu, s, 1);
      if (lane < 25) ls[(px * 4 + h4) * 26 + lane] = e / (1e-10f + s);
    }
  }
  __syncthreads();

  // ---- P2a: v halo (hg0), accumulate + store ch 0-127 ----
  load_halo(g_v, 0);
  __syncthreads();
  do_accum(0);
  __syncthreads();
  // ---- P2b: v halo (hg1), accumulate + store ch 128-255 ----
  load_halo(g_v, 1);
  __syncthreads();
  do_accum(1);
}

// ---------------------------------------------------------------------------
extern "C" void kernel_launch(void* const* d_in, const int* in_sizes, int n_in,
                              void* d_out, int out_size) {
  (void)in_sizes; (void)n_in; (void)out_size;
  const float* x = (const float*)d_in[0];
  const float* sims = (const float*)d_in[1];
  const float* Wq = (const float*)d_in[3];
  const float* Wk = (const float*)d_in[4];
  const float* Wv = (const float*)d_in[5];
  const float* Wp = (const float*)d_in[6];
  float* out = (float*)d_out;

  const int smem_cx = 256 * 65 * sizeof(float);
  const int smem_gm = 1024 + 163840 + 16896;
  const int smem_at = 28800 * sizeof(float);  // 115200 B -> 2 blocks/SM
  cudaFuncSetAttribute(conv_x, cudaFuncAttributeMaxDynamicSharedMemorySize, smem_cx);
  cudaFuncSetAttribute(gemm_kernel, cudaFuncAttributeMaxDynamicSharedMemorySize, smem_gm);
  cudaFuncSetAttribute(attn_kernel, cudaFuncAttributeMaxDynamicSharedMemorySize, smem_at);

  __nv_bfloat16 *px2, *po2, *pw1, *pw2;
  cudaGetSymbolAddress((void**)&px2, g_x2);
  cudaGetSymbolAddress((void**)&po2, g_o2);
  cudaGetSymbolAddress((void**)&pw1, g_w1);
  cudaGetSymbolAddress((void**)&pw2, g_w2);

  conv_x<<<NPIX / 64, 256, smem_cx>>>(x);
  conv_w<<<1024, 256>>>(Wq, Wk, Wv, Wp);
  gemm_kernel<<<NPIX / 128, 256, smem_gm>>>(px2, pw1, nullptr, 0);
  attn_kernel<<<4096, 512, smem_at>>>(sims);
  gemm_kernel<<<NPIX / 128, 256, smem_gm>>>(po2, pw2, out, 1);
}

// round 8
// speedup vs baseline: 1.6701x; 1.6701x over previous
#include <cuda_runtime.h>
#include <cuda_bf16.h>
#include <cstdint>

// ---------------------------------------------------------------------------
// SuperpixelAttention GB300 — Round 7: R5 tiled attention + cp.async halo
// pipelining (k-halo hidden behind simdot, v-halo hidden behind softmax).
//   conv_x : x fp32 -> g_x2 [pix][hi256|lo256] bf16
//   conv_w : Wq|Wk|Wv -> g_w1 (q scale folded), Wp -> g_w2
//   gemm(0): q/k/v fp32 (mma.sync bf16 3-term split)
//   attn   : 16x4 px tiles, 512 thr, k/v halo in smem, writes g_o2 bf16 hi|lo
//   gemm(1): out = o @ Wp, transposed store to [T,C,H,W]
// ---------------------------------------------------------------------------

#define NPIX 262144
#define NELEM 67108864

__device__ float g_q[NELEM];
__device__ float g_k[NELEM];
__device__ float g_v[NELEM];
__device__ __nv_bfloat16 g_x2[NPIX * 512];
__device__ __nv_bfloat16 g_o2[NPIX * 512];
__device__ __nv_bfloat16 g_w1[768 * 512];
__device__ __nv_bfloat16 g_w2[256 * 512];

__device__ __forceinline__ uint32_t smem_u32(const void* p) {
  uint32_t a;
  asm("{ .reg .u64 t; cvta.to.shared.u64 t, %1; cvt.u32.u64 %0, t; }"
      : "=r"(a) : "l"(p));
  return a;
}
#define SW128(o) ((o) ^ (((o) >> 3) & 0x70))

__device__ __forceinline__ void ldsm4(uint32_t& r0, uint32_t& r1, uint32_t& r2,
                                      uint32_t& r3, uint32_t a) {
  asm volatile("ldmatrix.sync.aligned.m8n8.x4.shared.b16 {%0,%1,%2,%3}, [%4];"
               : "=r"(r0), "=r"(r1), "=r"(r2), "=r"(r3) : "r"(a));
}
__device__ __forceinline__ void mma16816(float* c, const uint32_t* a,
                                         const uint32_t* b) {
  asm volatile(
      "mma.sync.aligned.m16n8k16.row.col.f32.bf16.bf16.f32 "
      "{%0,%1,%2,%3},{%4,%5,%6,%7},{%8,%9},{%0,%1,%2,%3};"
      : "+f"(c[0]), "+f"(c[1]), "+f"(c[2]), "+f"(c[3])
      : "r"(a[0]), "r"(a[1]), "r"(a[2]), "r"(a[3]), "r"(b[0]), "r"(b[1]));
}
__device__ __forceinline__ void cp16(uint32_t s, const void* g) {
  asm volatile("cp.async.cg.shared.global [%0], [%1], 16;" :: "r"(s), "l"(g));
}
#define CP_COMMIT() asm volatile("cp.async.commit_group;" ::: "memory")
#define CP_WAIT0()  asm volatile("cp.async.wait_group 0;" ::: "memory")

// ---------------------------------------------------------------------------
// Conversions
// ---------------------------------------------------------------------------
__global__ void __launch_bounds__(256) conv_x(const float* __restrict__ x) {
  extern __shared__ float xs[];  // 256 * 65
  const int tid = threadIdx.x;
  const int pix0 = blockIdx.x * 64;
  const int t = pix0 >> 16, h = (pix0 >> 8) & 255, w0 = pix0 & 255;
  const size_t base = (size_t)t * 16777216 + h * 256 + w0;
  for (int i = tid; i < 16384; i += 256) {
    int c = i >> 6, p = i & 63;
    xs[c * 65 + p] = x[base + (size_t)c * 65536 + p];
  }
  __syncthreads();
  for (int i = tid; i < 32768; i += 256) {
    int p = i >> 9, kk = i & 511, c = kk & 255;
    float v = xs[c * 65 + p];
    __nv_bfloat16 hi = __float2bfloat16_rn(v);
    __nv_bfloat16 o = (kk < 256) ? hi : __float2bfloat16_rn(v - __bfloat162float(hi));
    g_x2[(size_t)(pix0 + p) * 512 + kk] = o;
  }
}

__global__ void __launch_bounds__(256) conv_w(const float* __restrict__ Wq,
                                              const float* __restrict__ Wk,
                                              const float* __restrict__ Wv,
                                              const float* __restrict__ Wp) {
  const int n = blockIdx.x;   // 0..1023
  const int c = threadIdx.x;
  float v;
  __nv_bfloat16* dst;
  if (n < 768) {
    const float* Wm = (n < 256) ? Wq : ((n < 512) ? Wk : Wv);
    v = Wm[c * 256 + (n & 255)];
    if (n < 256) v *= 0.125f;  // fold hd^-0.5 into Wq
    dst = g_w1 + (size_t)n * 512;
  } else {
    v = Wp[c * 256 + (n & 255)];
    dst = g_w2 + (size_t)(n - 768) * 512;
  }
  __nv_bfloat16 hi = __float2bfloat16_rn(v);
  dst[c] = hi;
  dst[256 + c] = __float2bfloat16_rn(v - __bfloat162float(hi));
}

// ---------------------------------------------------------------------------
// mma.sync GEMM (unchanged from R4)
// ---------------------------------------------------------------------------
__global__ void __launch_bounds__(256) gemm_kernel(
    const __nv_bfloat16* __restrict__ A2,
    const __nv_bfloat16* __restrict__ B2,
    float* __restrict__ y, int mode) {
  extern __shared__ char dsm[];
  char* base = (char*)((((uintptr_t)dsm) + 1023) & ~(uintptr_t)1023);
  const uint32_t As_a = smem_u32(base);
  const uint32_t Bs_a0 = As_a + 131072u;
  float* ys = (float*)(base + 163840);

  const int tid = threadIdx.x, lane = tid & 31, wid = tid >> 5;
  const int wm = wid & 1, wn = wid >> 1;
  const int pix0 = blockIdx.x * 128;

  const uint4* Aq = (const uint4*)A2;
  for (int idx = tid; idx < 8192; idx += 256) {
    int ch = idx >> 10, row = (idx >> 3) & 127, c = idx & 7;
    *(uint4*)(base + ch * 16384 + SW128((uint32_t)(row * 128 + c * 16))) =
        Aq[(size_t)(pix0 + row) * 64 + ch * 8 + c];
  }

  const uint4* Bq = (const uint4*)B2;
  const int total = (mode ? 2 : 6) * 12;

  auto prefetchB = [&](int q) {
    int kc2 = q % 12, term = kc2 >> 2;
    int n0g = (q / 12) << 7;
    int b8 = ((term == 1) ? 32 : 0) + (kc2 & 3) * 8;
    uint32_t buf = Bs_a0 + (uint32_t)((q & 1) << 14);
    for (int idx = tid; idx < 1024; idx += 256) {
      int row = idx >> 3, c = idx & 7;
      cp16(buf + SW128((uint32_t)(row * 128 + c * 16)),
           &Bq[(size_t)(n0g + row) * 64 + b8 + c]);
    }
    CP_COMMIT();
  };

  float acc[4][4][4];
#pragma unroll
  for (int i = 0; i < 4; i++)
#pragma unroll
    for (int j = 0; j < 4; j++)
#pragma unroll
      for (int r = 0; r < 4; r++) acc[i][j][r] = 0.f;

  prefetchB(0);

  const int arow_off = (lane & 7) + ((lane >> 3) & 1) * 8;
  const int ak_ex = ((lane >> 4) & 1) * 16;
  const int brow_off = (lane & 7) + ((lane >> 4) & 1) * 8;
  const int bk_ex = ((lane >> 3) & 1) * 16;

  for (int q = 0; q < total; ++q) {
    if (q + 1 < total) {
      prefetchB(q + 1);
      asm volatile("cp.async.wait_group 1;" ::: "memory");
    } else {
      CP_WAIT0();
    }
    __syncthreads();

    const int kc2 = q % 12, term = kc2 >> 2;
    const uint32_t Ab = As_a + (uint32_t)((((term == 2) ? 4 : 0) + (kc2 & 3)) * 16384);
    const uint32_t Bb = Bs_a0 + (uint32_t)((q & 1) << 14);

#pragma unroll
    for (int s = 0; s < 4; ++s) {
      uint32_t af[4][4];
#pragma unroll
      for (int i = 0; i < 4; ++i) {
        uint32_t off = (uint32_t)((wm * 64 + i * 16 + arow_off) * 128 + s * 32 + ak_ex);
        ldsm4(af[i][0], af[i][1], af[i][2], af[i][3], Ab + SW128(off));
      }
      uint32_t bf[4][2];
#pragma unroll
      for (int j2 = 0; j2 < 2; ++j2) {
        uint32_t off = (uint32_t)((wn * 32 + j2 * 16 + brow_off) * 128 + s * 32 + bk_ex);
        ldsm4(bf[2 * j2][0], bf[2 * j2][1], bf[2 * j2 + 1][0], bf[2 * j2 + 1][1],
              Bb + SW128(off));
      }
#pragma unroll
      for (int i = 0; i < 4; ++i)
#pragma unroll
        for (int j = 0; j < 4; ++j) mma16816(acc[i][j], af[i], bf[j]);
    }

    if (kc2 == 11) {
      const int nc = q / 12;
      if (mode == 0) {
        float* dst = (nc < 2) ? g_q : (nc < 4) ? g_k : g_v;
        const int colb = (nc & 1) * 128 + wn * 32;
#pragma unroll
        for (int i = 0; i < 4; ++i) {
          int row0 = pix0 + wm * 64 + i * 16 + (lane >> 2);
#pragma unroll
          for (int j = 0; j < 4; ++j) {
            int col = colb + j * 8 + 2 * (lane & 3);
            *(float2*)(dst + (size_t)row0 * 256 + col) =
                make_float2(acc[i][j][0], acc[i][j][1]);
            *(float2*)(dst + (size_t)(row0 + 8) * 256 + col) =
                make_float2(acc[i][j][2], acc[i][j][3]);
          }
        }
      } else {
        const int t = pix0 >> 16, h = (pix0 >> 8) & 255, w0 = pix0 & 255;
        float* yb = y + (size_t)t * 16777216 + h * 256 + w0;
        for (int g = 0; g < 4; ++g) {
          if (wn == g) {
#pragma unroll
            for (int i = 0; i < 4; ++i) {
              int row0 = wm * 64 + i * 16 + (lane >> 2);
#pragma unroll
              for (int j = 0; j < 4; ++j) {
                int cl = j * 8 + 2 * (lane & 3);
                ys[cl * 132 + row0] = acc[i][j][0];
                ys[(cl + 1) * 132 + row0] = acc[i][j][1];
                ys[cl * 132 + row0 + 8] = acc[i][j][2];
                ys[(cl + 1) * 132 + row0 + 8] = acc[i][j][3];
              }
            }
          }
          __syncthreads();
          const int chb = nc * 128 + g * 32;
          for (int idx = tid; idx < 4096; idx += 256) {
            int cl = idx >> 7, p = idx & 127;
            yb[(size_t)(chb + cl) * 65536 + p] = ys[cl * 132 + p];
          }
          __syncthreads();
        }
      }
#pragma unroll
      for (int i = 0; i < 4; i++)
#pragma unroll
        for (int j = 0; j < 4; j++)
#pragma unroll
          for (int r = 0; r < 4; r++) acc[i][j][r] = 0.f;
    }
    __syncthreads();
  }
}

// ---------------------------------------------------------------------------
// Tiled attention (R5 structure) + cp.async halo pipelining.
// Block = 16(w) x 4(h) pixels, 512 threads (16 warps).
// Phases: [cp.async k-halo || sims+simdot] -> logits -> [cp.async v-halo ||
// softmax] -> accumulate -> store g_o2 bf16 hi|lo.
// ---------------------------------------------------------------------------
__device__ __forceinline__ uint32_t packbf2(float a, float b) {
  __nv_bfloat162 h = __floats2bfloat162_rn(a, b);
  return *reinterpret_cast<uint32_t*>(&h);
}

__global__ void __launch_bounds__(512) attn_kernel(const float* __restrict__ sims) {
  extern __shared__ float sm[];
  float* hs = sm;             // 40960 floats (160 cells x 256 ch)
  float* ls = sm + 40960;     // 6656: logits/wts [64][4][26]
  float* sd = ls + 6656;      // 1664: simdot [64][26]
  float* ss = sd + 1664;      // 1440: sims halo [9][160]

  const int tid = threadIdx.x, lane = tid & 31, wid = tid >> 5;
  const int bw = blockIdx.x & 15;
  const int bh = (blockIdx.x >> 4) & 63;
  const int t = blockIdx.x >> 10;
  const int w0 = bw << 4, h0 = bh << 2;
  const uint32_t hs_a = smem_u32(hs);

  // async halo load: 160 cells x 1KB, 20 cp16 per thread
  auto halo_async = [&](const float* src) {
    const char* s = (const char*)src;
#pragma unroll 1
    for (int i = tid; i < 10240; i += 512) {
      int cell = i >> 6, c4 = i & 63;
      int rr = cell / 20, cc = cell - rr * 20;
      int gh = min(max(h0 - 2 + rr, 0), 255);
      int gw = min(max(w0 - 2 + cc, 0), 255);
      cp16(hs_a + (uint32_t)(cell * 1024 + c4 * 16),
           s + ((size_t)((t << 16) | (gh << 8) | gw) * 64 + c4) * 16);
    }
    CP_COMMIT();
  };

  // ---- P0: k halo async || sims halo + simdot ----
  halo_async(g_k);
  for (int i = tid; i < 1440; i += 512) {
    int s = i / 160, cell = i - s * 160;
    int rr = cell / 20, cc = cell - rr * 20;
    int gh = min(max(h0 - 2 + rr, 0), 255);
    int gw = min(max(w0 - 2 + cc, 0), 255);
    ss[i] = sims[(size_t)(((t * 9 + s) << 16) | (gh << 8) | gw)];
  }
  __syncthreads();  // ss visible
  for (int i = tid; i < 1600; i += 512) {
    int px = i / 25, tap = i - px * 25;
    int r = px >> 4, wc = px & 15;
    int di = tap / 5, dj = tap - di * 5;
    int ctr = (r + 2) * 20 + wc + 2;
    int nbc = (r + di) * 20 + wc + dj;
    float acc = 0.f;
#pragma unroll
    for (int s = 0; s < 9; ++s) acc += ss[s * 160 + ctr] * ss[s * 160 + nbc];
    sd[px * 26 + tap] = acc;
  }
  CP_WAIT0();
  __syncthreads();  // k halo + sd visible

  // ---- P1: logits ----
  const int r = wid & 3, seg = wid >> 2;
  const int hgrp = lane >> 3;
  const size_t pixg0 = (size_t)((t << 16) | ((h0 + r) << 8) | (w0 + (seg << 2)));
  const float4* qg = (const float4*)g_q;
  float4 qa[4], qb[4];
#pragma unroll
  for (int p = 0; p < 4; ++p) {
    qa[p] = qg[(pixg0 + p) * 64 + lane * 2];
    qb[p] = qg[(pixg0 + p) * 64 + lane * 2 + 1];
  }

#pragma unroll 1
  for (int di = 0; di < 5; ++di) {
#pragma unroll
    for (int j = 0; j < 8; ++j) {
      const float4* kr = (const float4*)(hs + ((r + di) * 20 + (seg << 2) + j) * 256);
      float4 ka = kr[lane * 2], kb = kr[lane * 2 + 1];
      const int plo = (j - 4 > 0) ? j - 4 : 0;
      const int phi = (j < 3) ? j : 3;
#pragma unroll
      for (int p = plo; p <= phi; ++p) {
        float d = qa[p].x * ka.x + qa[p].y * ka.y + qa[p].z * ka.z + qa[p].w * ka.w +
                  qb[p].x * kb.x + qb[p].y * kb.y + qb[p].z * kb.z + qb[p].w * kb.w;
        d += __shfl_xor_sync(0xffffffffu, d, 1);
        d += __shfl_xor_sync(0xffffffffu, d, 2);
        d += __shfl_xor_sync(0xffffffffu, d, 4);
        if ((lane & 7) == 0) {
          int px = (r << 4) + (seg << 2) + p;
          ls[(px * 4 + hgrp) * 26 + di * 5 + j - p] = d;
        }
      }
    }
  }
  __syncthreads();  // all warps done reading k halo; ls complete

  // ---- P2: v halo async || softmax + sim reweight (in place in ls) ----
  halo_async(g_v);
#pragma unroll 1
  for (int p = 0; p < 4; ++p) {
    const int px = (r << 4) + (seg << 2) + p;
#pragma unroll 1
    for (int h4 = 0; h4 < 4; ++h4) {
      float a = (lane < 25) ? ls[(px * 4 + h4) * 26 + lane] : -1e30f;
      float mx = a;
      mx = fmaxf(mx, __shfl_xor_sync(0xffffffffu, mx, 16));
      mx = fmaxf(mx, __shfl_xor_sync(0xffffffffu, mx, 8));
      mx = fmaxf(mx, __shfl_xor_sync(0xffffffffu, mx, 4));
      mx = fmaxf(mx, __shfl_xor_sync(0xffffffffu, mx, 2));
      mx = fmaxf(mx, __shfl_xor_sync(0xffffffffu, mx, 1));
      float e = (lane < 25) ? __expf(a - mx) * sd[px * 26 + lane] : 0.f;
      float s = e;
      s += __shfl_xor_sync(0xffffffffu, s, 16);
      s += __shfl_xor_sync(0xffffffffu, s, 8);
      s += __shfl_xor_sync(0xffffffffu, s, 4);
      s += __shfl_xor_sync(0xffffffffu, s, 2);
      s += __shfl_xor_sync(0xffffffffu, s, 1);
      if (lane < 25) ls[(px * 4 + h4) * 26 + lane] = e / (1e-10f + s);
    }
  }
  CP_WAIT0();
  __syncthreads();  // v halo + wts visible

  // ---- P3: weighted accumulate ----
  float acc[4][8];
#pragma unroll
  for (int p = 0; p < 4; ++p)
#pragma unroll
    for (int c = 0; c < 8; ++c) acc[p][c] = 0.f;

#pragma unroll 1
  for (int di = 0; di < 5; ++di) {
#pragma unroll
    for (int j = 0; j < 8; ++j) {
      const float4* vr = (const float4*)(hs + ((r + di) * 20 + (seg << 2) + j) * 256);
      float4 va = vr[lane * 2], vb = vr[lane * 2 + 1];
      const int plo = (j - 4 > 0) ? j - 4 : 0;
      const int phi = (j < 3) ? j : 3;
#pragma unroll
      for (int p = plo; p <= phi; ++p) {
        int px = (r << 4) + (seg << 2) + p;
        float wt = ls[(px * 4 + hgrp) * 26 + di * 5 + j - p];
        acc[p][0] += wt * va.x; acc[p][1] += wt * va.y;
        acc[p][2] += wt * va.z; acc[p][3] += wt * va.w;
        acc[p][4] += wt * vb.x; acc[p][5] += wt * vb.y;
        acc[p][6] += wt * vb.z; acc[p][7] += wt * vb.w;
      }
    }
  }

  // ---- store g_o2 bf16 hi|lo directly ----
  uint4* oq = (uint4*)g_o2;
#pragma unroll
  for (int p = 0; p < 4; ++p) {
    float hi[8], lo[8];
#pragma unroll
    for (int c = 0; c < 8; ++c) {
      hi[c] = __bfloat162float(__float2bfloat16_rn(acc[p][c]));
      lo[c] = acc[p][c] - hi[c];
    }
    uint4 hv, lv;
    hv.x = packbf2(hi[0], hi[1]); hv.y = packbf2(hi[2], hi[3]);
    hv.z = packbf2(hi[4], hi[5]); hv.w = packbf2(hi[6], hi[7]);
    lv.x = packbf2(lo[0], lo[1]); lv.y = packbf2(lo[2], lo[3]);
    lv.z = packbf2(lo[4], lo[5]); lv.w = packbf2(lo[6], lo[7]);
    oq[(pixg0 + p) * 64 + lane] = hv;
    oq[(pixg0 + p) * 64 + 32 + lane] = lv;
  }
}

// ---------------------------------------------------------------------------
extern "C" void kernel_launch(void* const* d_in, const int* in_sizes, int n_in,
                              void* d_out, int out_size) {
  (void)in_sizes; (void)n_in; (void)out_size;
  const float* x = (const float*)d_in[0];
  const float* sims = (const float*)d_in[1];
  const float* Wq = (const float*)d_in[3];
  const float* Wk = (const float*)d_in[4];
  const float* Wv = (const float*)d_in[5];
  const float* Wp = (const float*)d_in[6];
  float* out = (float*)d_out;

  const int smem_cx = 256 * 65 * sizeof(float);
  const int smem_gm = 1024 + 163840 + 16896;
  const int smem_at = 50720 * sizeof(float);  // 202880 B
  cudaFuncSetAttribute(conv_x, cudaFuncAttributeMaxDynamicSharedMemorySize, smem_cx);
  cudaFuncSetAttribute(gemm_kernel, cudaFuncAttributeMaxDynamicSharedMemorySize, smem_gm);
  cudaFuncSetAttribute(attn_kernel, cudaFuncAttributeMaxDynamicSharedMemorySize, smem_at);

  __nv_bfloat16 *px2, *po2, *pw1, *pw2;
  cudaGetSymbolAddress((void**)&px2, g_x2);
  cudaGetSymbolAddress((void**)&po2, g_o2);
  cudaGetSymbolAddress((void**)&pw1, g_w1);
  cudaGetSymbolAddress((void**)&pw2, g_w2);

  conv_x<<<NPIX / 64, 256, smem_cx>>>(x);
  conv_w<<<1024, 256>>>(Wq, Wk, Wv, Wp);
  gemm_kernel<<<NPIX / 128, 256, smem_gm>>>(px2, pw1, nullptr, 0);
  attn_kernel<<<4096, 512, smem_at>>>(sims);
  gemm_kernel<<<NPIX / 128, 256, smem_gm>>>(po2, pw2, out, 1);
}